// round 9
// baseline (speedup 1.0000x reference)
#include <cuda_runtime.h>
#include <cuda_fp16.h>
#include <math.h>
#include <stdint.h>

#define D_MODEL 1024
#define NH      16
#define DH      64
#define BATCH   2
#define SEQ     2048
#define NTOK    (BATCH * SEQ)   // 4096

// Scratch (device globals — no runtime allocation allowed)
__device__ __half g_xh [NTOK * D_MODEL];       // x in fp16
__device__ __half g_wqh[D_MODEL * D_MODEL];
__device__ __half g_wkh[D_MODEL * D_MODEL];
__device__ __half g_wvh[D_MODEL * D_MODEL];
__device__ __half g_woh[D_MODEL * D_MODEL];
__device__ __half g_q16 [NTOK * D_MODEL];      // Q fp16, pre-scaled by 0.125*log2(e)
__device__ __half g_k16 [NTOK * D_MODEL];      // K fp16 [token][chan]
__device__ __half g_vt16[D_MODEL * NTOK];      // V^T fp16 [chan][token]
__device__ __half g_ctx [NTOK * D_MODEL];      // attention output fp16

__device__ __forceinline__ uint32_t smem_u32(const void* p) {
    uint32_t a;
    asm("{ .reg .u64 t; cvta.to.shared.u64 t, %1; cvt.u32.u64 %0, t; }" : "=r"(a) : "l"(p));
    return a;
}
__device__ __forceinline__ void ldsm_x4(uint32_t (&r)[4], uint32_t addr) {
    asm volatile("ldmatrix.sync.aligned.m8n8.x4.shared.b16 {%0,%1,%2,%3}, [%4];"
                 : "=r"(r[0]), "=r"(r[1]), "=r"(r[2]), "=r"(r[3]) : "r"(addr));
}
// fp16 mma with fp32 accumulate
__device__ __forceinline__ void mma_f16(float (&c)[4], const uint32_t a[4],
                                        uint32_t b0, uint32_t b1) {
    asm volatile(
        "mma.sync.aligned.m16n8k16.row.col.f32.f16.f16.f32 "
        "{%0,%1,%2,%3}, {%4,%5,%6,%7}, {%8,%9}, {%0,%1,%2,%3};"
        : "+f"(c[0]), "+f"(c[1]), "+f"(c[2]), "+f"(c[3])
        : "r"(a[0]), "r"(a[1]), "r"(a[2]), "r"(a[3]), "r"(b0), "r"(b1));
}
__device__ __forceinline__ float ex2(float x) {
    float y; asm("ex2.approx.f32 %0, %1;" : "=f"(y) : "f"(x)); return y;
}
#define CP_ASYNC16(dst, src) \
    asm volatile("cp.async.cg.shared.global [%0], [%1], 16;" :: "r"(dst), "l"(src) : "memory")
#define CP_COMMIT() asm volatile("cp.async.commit_group;" ::: "memory")
#define CP_WAIT0()  asm volatile("cp.async.wait_group 0;" ::: "memory")
#define CP_WAIT1()  asm volatile("cp.async.wait_group 1;" ::: "memory")

// ============================================================================
// fp32 -> fp16 conversion. Single-tensor variant (x) and 4-way variant (Ws).
// ============================================================================
__global__ __launch_bounds__(256) void f2h(const float* __restrict__ in,
                                           __half* __restrict__ out, int n)
{
    int i = (blockIdx.x * 256 + threadIdx.x) * 4;
    if (i < n) {
        float4 v = *reinterpret_cast<const float4*>(in + i);
        __half2 h0 = __floats2half2_rn(v.x, v.y);
        __half2 h1 = __floats2half2_rn(v.z, v.w);
        uint2 pk = make_uint2(*reinterpret_cast<uint32_t*>(&h0),
                              *reinterpret_cast<uint32_t*>(&h1));
        *reinterpret_cast<uint2*>(out + i) = pk;
    }
}
__global__ __launch_bounds__(256) void f2h4(
    const float* __restrict__ i0, const float* __restrict__ i1,
    const float* __restrict__ i2, const float* __restrict__ i3,
    __half* __restrict__ o0, __half* __restrict__ o1,
    __half* __restrict__ o2, __half* __restrict__ o3, int n)
{
    const float* in  = (blockIdx.y == 0) ? i0 : (blockIdx.y == 1) ? i1
                     : (blockIdx.y == 2) ? i2 : i3;
    __half* out      = (blockIdx.y == 0) ? o0 : (blockIdx.y == 1) ? o1
                     : (blockIdx.y == 2) ? o2 : o3;
    int i = (blockIdx.x * 256 + threadIdx.x) * 4;
    if (i < n) {
        float4 v = *reinterpret_cast<const float4*>(in + i);
        __half2 h0 = __floats2half2_rn(v.x, v.y);
        __half2 h1 = __floats2half2_rn(v.z, v.w);
        uint2 pk = make_uint2(*reinterpret_cast<uint32_t*>(&h0),
                              *reinterpret_cast<uint32_t*>(&h1));
        *reinterpret_cast<uint2*>(out + i) = pk;
    }
}

// ============================================================================
// fp16 tensor-core GEMM: C[M,N] = A[M,K] @ W[N,K]^T  (both fp16 row-major)
// CTA 128x128, BK=64, 256 threads = 8 warps (2x4), warp tile 64x32.
// MODE 0: fp32 out; MODE 1: fp16 out * QSCALE; MODE 2: fp16 out.
// ============================================================================
#define BM 128
#define BN 128
#define BKH 64
#define KSTRH 72                         // fp16 elems per smem row (144 B)
#define TILE_H (BM * KSTRH)              // fp16 per operand tile = 9216
#define GSMEM_BYTES (4 * TILE_H * 2)     // 73728

#define QSCALEF (0.125f * 1.4426950408889634f)

template <int MODE>
__global__ __launch_bounds__(256, 2) void hgemm(
    const __half* __restrict__ A, const __half* __restrict__ W,
    void* __restrict__ Cv, int M, int N, int K)
{
    extern __shared__ __half smh[];
    __half* AsP[2] = { smh,              smh + TILE_H };
    __half* BsP[2] = { smh + 2 * TILE_H, smh + 3 * TILE_H };

    const int tid  = threadIdx.x;
    const int wid  = tid >> 5;
    const int lane = tid & 31;
    const int bm   = blockIdx.y * BM;
    const int bn   = blockIdx.x * BN;
    const int wm = (wid >> 2) * 64;
    const int wn = (wid & 3) * 32;

    float acc[4][4][4];
#pragma unroll
    for (int i = 0; i < 4; i++)
#pragma unroll
        for (int j = 0; j < 4; j++)
#pragma unroll
            for (int q = 0; q < 4; q++) acc[i][j][q] = 0.f;

    const int aj   = lane >> 3;
    const int mrow = ((aj & 1) << 3) + (lane & 7);
    const int mcol = (aj >> 1) << 4;      // byte offset 0 or 16

    uint32_t aBase[2], bBase[2];
#pragma unroll
    for (int buf = 0; buf < 2; buf++) {
        aBase[buf] = smem_u32(AsP[buf]) + (uint32_t)(wm + mrow) * (KSTRH * 2) + mcol;
        bBase[buf] = smem_u32(BsP[buf]) + (uint32_t)(wn + mrow) * (KSTRH * 2) + mcol;
    }

    const __half* Ap = A + (size_t)bm * K;
    const __half* Wp = W + (size_t)bn * K;
    const int KT = K / BKH;   // 16

    auto load_tile = [&](int t, int buf) {
        const __half* Ag = Ap + t * BKH;
        const __half* Bg = Wp + t * BKH;
        uint32_t sa = smem_u32(AsP[buf]);
        uint32_t sb = smem_u32(BsP[buf]);
#pragma unroll
        for (int i = 0; i < 4; i++) {
            int chunk = tid + 256 * i;       // 0..1023
            int row = chunk >> 3;
            int c   = chunk & 7;             // 16B chunk within 128B row
            uint32_t so = (uint32_t)row * (KSTRH * 2) + c * 16;
            CP_ASYNC16(sa + so, __cvta_generic_to_global(Ag + (size_t)row * K + c * 8));
            CP_ASYNC16(sb + so, __cvta_generic_to_global(Bg + (size_t)row * K + c * 8));
        }
        CP_COMMIT();
    };

    load_tile(0, 0);

    for (int t = 0; t < KT; t++) {
        const int buf = t & 1;
        if (t + 1 < KT) { load_tile(t + 1, buf ^ 1); CP_WAIT1(); }
        else           { CP_WAIT0(); }
        __syncthreads();

#pragma unroll
        for (int ks = 0; ks < 4; ks++) {          // 4 x k16 per BK=64
            uint32_t afr[4][4], bfr[2][4];
#pragma unroll
            for (int mt = 0; mt < 4; mt++)
                ldsm_x4(afr[mt], aBase[buf] + (uint32_t)(mt * 16 * KSTRH * 2) + ks * 32);
#pragma unroll
            for (int p = 0; p < 2; p++)
                ldsm_x4(bfr[p], bBase[buf] + (uint32_t)(p * 16 * KSTRH * 2) + ks * 32);
#pragma unroll
            for (int mt = 0; mt < 4; mt++) {
#pragma unroll
                for (int p = 0; p < 2; p++) {
                    mma_f16(acc[mt][2 * p],     afr[mt], bfr[p][0], bfr[p][2]);
                    mma_f16(acc[mt][2 * p + 1], afr[mt], bfr[p][1], bfr[p][3]);
                }
            }
        }
        __syncthreads();
    }

    const int rr = lane >> 2;
    const int cc = (lane & 3) * 2;
#pragma unroll
    for (int mt = 0; mt < 4; mt++) {
#pragma unroll
        for (int nt = 0; nt < 4; nt++) {
            int row = bm + wm + mt * 16 + rr;
            int col = bn + wn + nt * 8 + cc;
            if (MODE == 0) {
                float* Cp = (float*)Cv;
                *reinterpret_cast<float2*>(Cp + (size_t)row * N + col)
                    = make_float2(acc[mt][nt][0], acc[mt][nt][1]);
                *reinterpret_cast<float2*>(Cp + (size_t)(row + 8) * N + col)
                    = make_float2(acc[mt][nt][2], acc[mt][nt][3]);
            } else {
                const float s = (MODE == 1) ? QSCALEF : 1.0f;
                __half* Cp = (__half*)Cv;
                __half2 v0 = __floats2half2_rn(acc[mt][nt][0] * s, acc[mt][nt][1] * s);
                __half2 v1 = __floats2half2_rn(acc[mt][nt][2] * s, acc[mt][nt][3] * s);
                *reinterpret_cast<__half2*>(Cp + (size_t)row * N + col)       = v0;
                *reinterpret_cast<__half2*>(Cp + (size_t)(row + 8) * N + col) = v1;
            }
        }
    }
}

// ============================================================================
// fp16 tensor-core causal flash attention (m16n8k16).
// R9: per-warp skip of fully-masked 16-token groups in the two diagonal
// ktiles (skip S ldsm+mma AND P.V ldsm+mma for those groups).
// smem: Q/P [128][72] fp16 | K x2 [64][72] | V^T x2 [64][72] = 54 KB -> 2 CTA/SM
// ============================================================================
#define ASTRH 72
#define AQ_OFF    0
#define AK_OFF(b) (128 * ASTRH + (b) * 64 * ASTRH)
#define AV_OFF(b) (128 * ASTRH + 2 * 64 * ASTRH + (b) * 64 * ASTRH)
#define AT_H      (128 * ASTRH + 4 * 64 * ASTRH)
#define AT_BYTES  (AT_H * 2)                 // 55296

__global__ __launch_bounds__(256, 2) void attn_mma(
    const __half* __restrict__ Q, const __half* __restrict__ Kp,
    const __half* __restrict__ Vt, __half* __restrict__ O)
{
    extern __shared__ __half smh[];
    const int tid  = threadIdx.x;
    const int wid  = tid >> 5;
    const int lane = tid & 31;
    const int qt   = (SEQ / 128 - 1) - blockIdx.x;   // long blocks first
    const int h    = blockIdx.y;
    const int b    = blockIdx.z;
    const int q0   = qt * 128;
    const int nkt  = 2 * qt + 2;
    const size_t hb = (size_t)b * SEQ * D_MODEL + (size_t)h * DH;

    auto load_k = [&](int kt, int buf) {
        uint32_t dst = smem_u32(smh + AK_OFF(buf));
        const __half* Kg = Kp + hb + (size_t)kt * 64 * D_MODEL;
#pragma unroll
        for (int i = 0; i < 2; i++) {
            int chunk = tid + 256 * i;       // 0..511
            int row = chunk >> 3, c = chunk & 7;
            CP_ASYNC16(dst + (uint32_t)row * (ASTRH * 2) + c * 16,
                       __cvta_generic_to_global(Kg + (size_t)row * D_MODEL + c * 8));
        }
    };
    auto load_v = [&](int kt, int buf) {
        uint32_t dst = smem_u32(smh + AV_OFF(buf));
        const __half* Vg = Vt + (size_t)h * 64 * NTOK + (size_t)b * SEQ + (size_t)kt * 64;
#pragma unroll
        for (int i = 0; i < 2; i++) {
            int chunk = tid + 256 * i;
            int d = chunk >> 3, c = chunk & 7;
            CP_ASYNC16(dst + (uint32_t)d * (ASTRH * 2) + c * 16,
                       __cvta_generic_to_global(Vg + (size_t)d * NTOK + c * 8));
        }
    };

    // prologue: Q (group0), K0+V0 (group1)
    {
        uint32_t qdst = smem_u32(smh + AQ_OFF);
#pragma unroll
        for (int i = 0; i < 4; i++) {
            int chunk = tid + 256 * i;       // 0..1023
            int row = chunk >> 3, c = chunk & 7;
            CP_ASYNC16(qdst + (uint32_t)row * (ASTRH * 2) + c * 16,
                       __cvta_generic_to_global(Q + hb + (size_t)(q0 + row) * D_MODEL + c * 8));
        }
        CP_COMMIT();
    }
    load_k(0, 0);
    load_v(0, 0);
    CP_COMMIT();

    const int aj   = lane >> 3;
    const int mrow = ((aj & 1) << 3) + (lane & 7);
    const int mcol = (aj >> 1) << 4;
    const int wq   = wid * 16;

    CP_WAIT1();
    __syncthreads();

    // Preload Q fragments (pre-scaled in GEMM epilogue): 4 k16-steps
    uint32_t qfr[4][4];
    {
        uint32_t qa = smem_u32(smh + AQ_OFF) + (uint32_t)(wq + mrow) * (ASTRH * 2) + mcol;
#pragma unroll
        for (int ks = 0; ks < 4; ks++) ldsm_x4(qfr[ks], qa + ks * 32);
    }
    // Q smem region reused as P (all threads hold Q frags; pass loop-top sync)

    __half* Ps = smh + AQ_OFF;
    const uint32_t pLd = smem_u32(Ps) + (uint32_t)(wq + mrow) * (ASTRH * 2) + mcol;
    const uint32_t kB[2] = { smem_u32(smh + AK_OFF(0)) + (uint32_t)mrow * (ASTRH * 2) + mcol,
                             smem_u32(smh + AK_OFF(1)) + (uint32_t)mrow * (ASTRH * 2) + mcol };
    const uint32_t vB[2] = { smem_u32(smh + AV_OFF(0)) + (uint32_t)mrow * (ASTRH * 2) + mcol,
                             smem_u32(smh + AV_OFF(1)) + (uint32_t)mrow * (ASTRH * 2) + mcol };

    float oacc[8][4];
#pragma unroll
    for (int nt = 0; nt < 8; nt++)
#pragma unroll
        for (int r = 0; r < 4; r++) oacc[nt][r] = 0.f;
    float m0 = -INFINITY, m1 = -INFINITY, l0 = 0.f, l1 = 0.f;

    const int lr = lane >> 2;
    const int lc = (lane & 3) * 2;

    for (int kt = 0; kt < nkt; kt++) {
        const int buf = kt & 1;
        const int k0  = kt * 64;
        CP_WAIT0();
        __syncthreads();

        if (kt + 1 < nkt) {
            load_k(kt + 1, buf ^ 1);
            load_v(kt + 1, buf ^ 1);
            CP_COMMIT();
        }

        // per-warp live 16-token-group count in this tile (4 = all live)
        int plim = 4;
        if (kt >= 2 * qt) {
            int d = ((wq + 15 - (k0 - q0)) >> 4) + 1;   // arithmetic shift = floor
            plim = d < 0 ? 0 : (d > 4 ? 4 : d);
        }

        // ---- S = Q K^T : skip fully-masked token groups ----
        float sacc[8][4];
#pragma unroll
        for (int nt = 0; nt < 8; nt++)
#pragma unroll
            for (int r = 0; r < 4; r++) sacc[nt][r] = 0.f;

#pragma unroll
        for (int ks = 0; ks < 4; ks++) {
#pragma unroll
            for (int p = 0; p < 4; p++) {
                if (p < plim) {
                    uint32_t kf[4];
                    ldsm_x4(kf, kB[buf] + (uint32_t)(p * 16 * ASTRH * 2) + ks * 32);
                    mma_f16(sacc[2 * p],     qfr[ks], kf[0], kf[2]);
                    mma_f16(sacc[2 * p + 1], qfr[ks], kf[1], kf[3]);
                }
            }
        }

        const int rg0 = q0 + wq + lr;
        if (kt >= 2 * qt) {
#pragma unroll
            for (int nt = 0; nt < 8; nt++) {
                int cb = k0 + nt * 8 + lc;
                if (cb     > rg0)     sacc[nt][0] = -1e30f;
                if (cb + 1 > rg0)     sacc[nt][1] = -1e30f;
                if (cb     > rg0 + 8) sacc[nt][2] = -1e30f;
                if (cb + 1 > rg0 + 8) sacc[nt][3] = -1e30f;
            }
        }

        // ---- online softmax (log2 domain) ----
        float mx0 = -1e30f, mx1 = -1e30f;
#pragma unroll
        for (int nt = 0; nt < 8; nt++) {
            mx0 = fmaxf(mx0, fmaxf(sacc[nt][0], sacc[nt][1]));
            mx1 = fmaxf(mx1, fmaxf(sacc[nt][2], sacc[nt][3]));
        }
        mx0 = fmaxf(mx0, __shfl_xor_sync(0xffffffffu, mx0, 1));
        mx0 = fmaxf(mx0, __shfl_xor_sync(0xffffffffu, mx0, 2));
        mx1 = fmaxf(mx1, __shfl_xor_sync(0xffffffffu, mx1, 1));
        mx1 = fmaxf(mx1, __shfl_xor_sync(0xffffffffu, mx1, 2));
        float mn0 = fmaxf(m0, mx0), mn1 = fmaxf(m1, mx1);
        float a0 = ex2(m0 - mn0), a1 = ex2(m1 - mn1);
        float rs0 = 0.f, rs1 = 0.f;
#pragma unroll
        for (int nt = 0; nt < 8; nt++) {
            float e0 = ex2(sacc[nt][0] - mn0);
            float e1 = ex2(sacc[nt][1] - mn0);
            float e2 = ex2(sacc[nt][2] - mn1);
            float e3 = ex2(sacc[nt][3] - mn1);
            sacc[nt][0] = e0; sacc[nt][1] = e1; sacc[nt][2] = e2; sacc[nt][3] = e3;
            rs0 += e0 + e1; rs1 += e2 + e3;
        }
        rs0 += __shfl_xor_sync(0xffffffffu, rs0, 1);
        rs0 += __shfl_xor_sync(0xffffffffu, rs0, 2);
        rs1 += __shfl_xor_sync(0xffffffffu, rs1, 1);
        rs1 += __shfl_xor_sync(0xffffffffu, rs1, 2);
        l0 = l0 * a0 + rs0; m0 = mn0;
        l1 = l1 * a1 + rs1; m1 = mn1;
#pragma unroll
        for (int nt = 0; nt < 8; nt++) {
            oacc[nt][0] *= a0; oacc[nt][1] *= a0;
            oacc[nt][2] *= a1; oacc[nt][3] *= a1;
        }

        // ---- stash P as fp16 (warp-local rows) ----
        {
            __half* pr0 = Ps + (wq + lr) * ASTRH + lc;
            __half* pr1 = pr0 + 8 * ASTRH;
#pragma unroll
            for (int nt = 0; nt < 8; nt++) {
                *reinterpret_cast<__half2*>(pr0 + nt * 8)
                    = __floats2half2_rn(sacc[nt][0], sacc[nt][1]);
                *reinterpret_cast<__half2*>(pr1 + nt * 8)
                    = __floats2half2_rn(sacc[nt][2], sacc[nt][3]);
            }
        }
        __syncwarp();

        // ---- O += P V : skip token groups whose P is exactly zero ----
#pragma unroll
        for (int ks = 0; ks < 4; ks++) {
            if (ks < plim) {
                uint32_t pf[4];
                ldsm_x4(pf, pLd + ks * 32);
#pragma unroll
                for (int p = 0; p < 4; p++) {
                    uint32_t vf[4];
                    ldsm_x4(vf, vB[buf] + (uint32_t)(p * 16 * ASTRH * 2) + ks * 32);
                    mma_f16(oacc[2 * p],     pf, vf[0], vf[2]);
                    mma_f16(oacc[2 * p + 1], pf, vf[1], vf[3]);
                }
            }
        }
    }

    // ---- epilogue: fp16 ctx ----
    const float i0 = 1.f / l0, i1 = 1.f / l1;
    const int row0 = q0 + wq + lr;
    __half* Ob = O + (size_t)(b * SEQ + row0) * D_MODEL + (size_t)h * DH + lc;
#pragma unroll
    for (int nt = 0; nt < 8; nt++) {
        *reinterpret_cast<__half2*>(Ob + nt * 8)
            = __floats2half2_rn(oacc[nt][0] * i0, oacc[nt][1] * i0);
        *reinterpret_cast<__half2*>(Ob + 8 * D_MODEL + nt * 8)
            = __floats2half2_rn(oacc[nt][2] * i1, oacc[nt][3] * i1);
    }
}

// ---------------------------------------------------------------------------
extern "C" void kernel_launch(void* const* d_in, const int* in_sizes, int n_in,
                              void* d_out, int out_size)
{
    const float* x  = (const float*)d_in[0];
    const float* Wq = (const float*)d_in[1];
    const float* Wk = (const float*)d_in[2];
    const float* Wv = (const float*)d_in[3];
    const float* Wo = (const float*)d_in[4];
    float* out = (float*)d_out;

    __half *xh, *wqh, *wkh, *wvh, *woh, *q16, *k16, *vt16, *ctx;
    cudaGetSymbolAddress((void**)&xh,   g_xh);
    cudaGetSymbolAddress((void**)&wqh,  g_wqh);
    cudaGetSymbolAddress((void**)&wkh,  g_wkh);
    cudaGetSymbolAddress((void**)&wvh,  g_wvh);
    cudaGetSymbolAddress((void**)&woh,  g_woh);
    cudaGetSymbolAddress((void**)&q16,  g_q16);
    cudaGetSymbolAddress((void**)&k16,  g_k16);
    cudaGetSymbolAddress((void**)&vt16, g_vt16);
    cudaGetSymbolAddress((void**)&ctx,  g_ctx);

    cudaFuncSetAttribute(hgemm<0>, cudaFuncAttributeMaxDynamicSharedMemorySize, GSMEM_BYTES);
    cudaFuncSetAttribute(hgemm<1>, cudaFuncAttributeMaxDynamicSharedMemorySize, GSMEM_BYTES);
    cudaFuncSetAttribute(hgemm<2>, cudaFuncAttributeMaxDynamicSharedMemorySize, GSMEM_BYTES);
    cudaFuncSetAttribute(attn_mma, cudaFuncAttributeMaxDynamicSharedMemorySize, AT_BYTES);

    // fp32 -> fp16 conversions: 2 launches total
    const int NX = NTOK * D_MODEL, NW = D_MODEL * D_MODEL;
    f2h<<<NX / 1024, 256>>>(x, xh, NX);
    f2h4<<<dim3(NW / 1024, 4), 256>>>(Wq, Wk, Wv, Wo, wqh, wkh, wvh, woh, NW);

    dim3 gg (D_MODEL / BN, NTOK / BM);   // (8, 32)  — token-major outputs
    dim3 ggT(NTOK / BN, D_MODEL / BM);   // (32, 8)  — V^T output

    hgemm<1><<<gg,  256, GSMEM_BYTES>>>(xh,  wqh, (void*)q16,  NTOK,    D_MODEL, D_MODEL);
    hgemm<2><<<gg,  256, GSMEM_BYTES>>>(xh,  wkh, (void*)k16,  NTOK,    D_MODEL, D_MODEL);
    hgemm<2><<<ggT, 256, GSMEM_BYTES>>>(wvh, xh,  (void*)vt16, D_MODEL, NTOK,    D_MODEL);

    attn_mma<<<dim3(SEQ / 128, NH, BATCH), 256, AT_BYTES>>>(q16, k16, vt16, ctx);

    hgemm<0><<<gg, 256, GSMEM_BYTES>>>(ctx, woh, (void*)out, NTOK, D_MODEL, D_MODEL);
}

// round 10
// speedup vs baseline: 1.0183x; 1.0183x over previous
#include <cuda_runtime.h>
#include <cuda_fp16.h>
#include <math.h>
#include <stdint.h>

#define D_MODEL 1024
#define NH      16
#define DH      64
#define BATCH   2
#define SEQ     2048
#define NTOK    (BATCH * SEQ)   // 4096

// Scratch (device globals — no runtime allocation allowed)
__device__ __half g_xh [NTOK * D_MODEL];       // x in fp16
__device__ __half g_wqh[D_MODEL * D_MODEL];
__device__ __half g_wkh[D_MODEL * D_MODEL];
__device__ __half g_wvh[D_MODEL * D_MODEL];
__device__ __half g_woh[D_MODEL * D_MODEL];
__device__ __half g_q16 [NTOK * D_MODEL];      // Q fp16, pre-scaled by 0.125*log2(e)
__device__ __half g_k16 [NTOK * D_MODEL];      // K fp16 [token][chan]
__device__ __half g_vt16[D_MODEL * NTOK];      // V^T fp16 [chan][token]
__device__ __half g_ctx [NTOK * D_MODEL];      // attention output fp16

__device__ __forceinline__ uint32_t smem_u32(const void* p) {
    uint32_t a;
    asm("{ .reg .u64 t; cvta.to.shared.u64 t, %1; cvt.u32.u64 %0, t; }" : "=r"(a) : "l"(p));
    return a;
}
__device__ __forceinline__ void ldsm_x4(uint32_t (&r)[4], uint32_t addr) {
    asm volatile("ldmatrix.sync.aligned.m8n8.x4.shared.b16 {%0,%1,%2,%3}, [%4];"
                 : "=r"(r[0]), "=r"(r[1]), "=r"(r[2]), "=r"(r[3]) : "r"(addr));
}
// fp16 mma with fp32 accumulate
__device__ __forceinline__ void mma_f16(float (&c)[4], const uint32_t a[4],
                                        uint32_t b0, uint32_t b1) {
    asm volatile(
        "mma.sync.aligned.m16n8k16.row.col.f32.f16.f16.f32 "
        "{%0,%1,%2,%3}, {%4,%5,%6,%7}, {%8,%9}, {%0,%1,%2,%3};"
        : "+f"(c[0]), "+f"(c[1]), "+f"(c[2]), "+f"(c[3])
        : "r"(a[0]), "r"(a[1]), "r"(a[2]), "r"(a[3]), "r"(b0), "r"(b1));
}
__device__ __forceinline__ float ex2(float x) {
    float y; asm("ex2.approx.f32 %0, %1;" : "=f"(y) : "f"(x)); return y;
}
#define CP_ASYNC16(dst, src) \
    asm volatile("cp.async.cg.shared.global [%0], [%1], 16;" :: "r"(dst), "l"(src) : "memory")
#define CP_COMMIT() asm volatile("cp.async.commit_group;" ::: "memory")
#define CP_WAIT0()  asm volatile("cp.async.wait_group 0;" ::: "memory")
#define CP_WAIT1()  asm volatile("cp.async.wait_group 1;" ::: "memory")

// ============================================================================
// fp32 -> fp16 conversion. Single-tensor variant (x) and 4-way variant (Ws).
// ============================================================================
__global__ __launch_bounds__(256) void f2h(const float* __restrict__ in,
                                           __half* __restrict__ out, int n)
{
    int i = (blockIdx.x * 256 + threadIdx.x) * 4;
    if (i < n) {
        float4 v = *reinterpret_cast<const float4*>(in + i);
        __half2 h0 = __floats2half2_rn(v.x, v.y);
        __half2 h1 = __floats2half2_rn(v.z, v.w);
        uint2 pk = make_uint2(*reinterpret_cast<uint32_t*>(&h0),
                              *reinterpret_cast<uint32_t*>(&h1));
        *reinterpret_cast<uint2*>(out + i) = pk;
    }
}
__global__ __launch_bounds__(256) void f2h4(
    const float* __restrict__ i0, const float* __restrict__ i1,
    const float* __restrict__ i2, const float* __restrict__ i3,
    __half* __restrict__ o0, __half* __restrict__ o1,
    __half* __restrict__ o2, __half* __restrict__ o3, int n)
{
    const float* in  = (blockIdx.y == 0) ? i0 : (blockIdx.y == 1) ? i1
                     : (blockIdx.y == 2) ? i2 : i3;
    __half* out      = (blockIdx.y == 0) ? o0 : (blockIdx.y == 1) ? o1
                     : (blockIdx.y == 2) ? o2 : o3;
    int i = (blockIdx.x * 256 + threadIdx.x) * 4;
    if (i < n) {
        float4 v = *reinterpret_cast<const float4*>(in + i);
        __half2 h0 = __floats2half2_rn(v.x, v.y);
        __half2 h1 = __floats2half2_rn(v.z, v.w);
        uint2 pk = make_uint2(*reinterpret_cast<uint32_t*>(&h0),
                              *reinterpret_cast<uint32_t*>(&h1));
        *reinterpret_cast<uint2*>(out + i) = pk;
    }
}

// ============================================================================
// fp16 tensor-core GEMM: C[M,N] = A[M,K] @ W[N,K]^T  (both fp16 row-major)
// R10: 3-stage cp.async pipeline, ONE __syncthreads per ktile.
// CTA 128x128, BK=64, 256 threads = 8 warps (2x4), warp tile 64x32.
// MODE 0: fp32 out; MODE 1: fp16 out * QSCALE; MODE 2: fp16 out.
// ============================================================================
#define BM 128
#define BN 128
#define BKH 64
#define KSTRH 72                           // fp16 elems per smem row (144 B)
#define TILE_H (BM * KSTRH)                // fp16 per operand tile = 9216
#define NSTAGE 3
#define GSMEM_BYTES (NSTAGE * 2 * TILE_H * 2)   // 110592 B = 108 KB

#define QSCALEF (0.125f * 1.4426950408889634f)

template <int MODE>
__global__ __launch_bounds__(256, 2) void hgemm(
    const __half* __restrict__ A, const __half* __restrict__ W,
    void* __restrict__ Cv, int M, int N, int K)
{
    extern __shared__ __half smh[];
    // stage s: A at s*2*TILE_H, B at s*2*TILE_H + TILE_H

    const int tid  = threadIdx.x;
    const int wid  = tid >> 5;
    const int lane = tid & 31;
    const int bm   = blockIdx.y * BM;
    const int bn   = blockIdx.x * BN;
    const int wm = (wid >> 2) * 64;
    const int wn = (wid & 3) * 32;

    float acc[4][4][4];
#pragma unroll
    for (int i = 0; i < 4; i++)
#pragma unroll
        for (int j = 0; j < 4; j++)
#pragma unroll
            for (int q = 0; q < 4; q++) acc[i][j][q] = 0.f;

    const int aj   = lane >> 3;
    const int mrow = ((aj & 1) << 3) + (lane & 7);
    const int mcol = (aj >> 1) << 4;      // byte offset 0 or 16

    uint32_t aBase[NSTAGE], bBase[NSTAGE];
#pragma unroll
    for (int s = 0; s < NSTAGE; s++) {
        aBase[s] = smem_u32(smh + s * 2 * TILE_H)
                 + (uint32_t)(wm + mrow) * (KSTRH * 2) + mcol;
        bBase[s] = smem_u32(smh + s * 2 * TILE_H + TILE_H)
                 + (uint32_t)(wn + mrow) * (KSTRH * 2) + mcol;
    }

    const __half* Ap = A + (size_t)bm * K;
    const __half* Wp = W + (size_t)bn * K;
    const int KT = K / BKH;   // 16

    auto load_tile = [&](int t, int s) {
        const __half* Ag = Ap + t * BKH;
        const __half* Bg = Wp + t * BKH;
        uint32_t sa = smem_u32(smh + s * 2 * TILE_H);
        uint32_t sb = smem_u32(smh + s * 2 * TILE_H + TILE_H);
#pragma unroll
        for (int i = 0; i < 4; i++) {
            int chunk = tid + 256 * i;       // 0..1023
            int row = chunk >> 3;
            int c   = chunk & 7;             // 16B chunk within 128B row
            uint32_t so = (uint32_t)row * (KSTRH * 2) + c * 16;
            CP_ASYNC16(sa + so, __cvta_generic_to_global(Ag + (size_t)row * K + c * 8));
            CP_ASYNC16(sb + so, __cvta_generic_to_global(Bg + (size_t)row * K + c * 8));
        }
        CP_COMMIT();
    };

    // prologue: stages 0,1 in flight
    load_tile(0, 0);
    load_tile(1, 1);

    for (int t = 0; t < KT; t++) {
        const int s = t % NSTAGE;
        if (t + 1 < KT) CP_WAIT1();   // tile t landed (tile t+1 may be in flight)
        else            CP_WAIT0();
        __syncthreads();              // tile t visible + stage (t+2)%3 fully consumed
        if (t + 2 < KT) load_tile(t + 2, (t + 2) % NSTAGE);

#pragma unroll
        for (int ks = 0; ks < 4; ks++) {          // 4 x k16 per BK=64
            uint32_t afr[4][4], bfr[2][4];
#pragma unroll
            for (int mt = 0; mt < 4; mt++)
                ldsm_x4(afr[mt], aBase[s] + (uint32_t)(mt * 16 * KSTRH * 2) + ks * 32);
#pragma unroll
            for (int p = 0; p < 2; p++)
                ldsm_x4(bfr[p], bBase[s] + (uint32_t)(p * 16 * KSTRH * 2) + ks * 32);
#pragma unroll
            for (int mt = 0; mt < 4; mt++) {
#pragma unroll
                for (int p = 0; p < 2; p++) {
                    mma_f16(acc[mt][2 * p],     afr[mt], bfr[p][0], bfr[p][2]);
                    mma_f16(acc[mt][2 * p + 1], afr[mt], bfr[p][1], bfr[p][3]);
                }
            }
        }
    }

    const int rr = lane >> 2;
    const int cc = (lane & 3) * 2;
#pragma unroll
    for (int mt = 0; mt < 4; mt++) {
#pragma unroll
        for (int nt = 0; nt < 4; nt++) {
            int row = bm + wm + mt * 16 + rr;
            int col = bn + wn + nt * 8 + cc;
            if (MODE == 0) {
                float* Cp = (float*)Cv;
                *reinterpret_cast<float2*>(Cp + (size_t)row * N + col)
                    = make_float2(acc[mt][nt][0], acc[mt][nt][1]);
                *reinterpret_cast<float2*>(Cp + (size_t)(row + 8) * N + col)
                    = make_float2(acc[mt][nt][2], acc[mt][nt][3]);
            } else {
                const float s2 = (MODE == 1) ? QSCALEF : 1.0f;
                __half* Cp = (__half*)Cv;
                __half2 v0 = __floats2half2_rn(acc[mt][nt][0] * s2, acc[mt][nt][1] * s2);
                __half2 v1 = __floats2half2_rn(acc[mt][nt][2] * s2, acc[mt][nt][3] * s2);
                *reinterpret_cast<__half2*>(Cp + (size_t)row * N + col)       = v0;
                *reinterpret_cast<__half2*>(Cp + (size_t)(row + 8) * N + col) = v1;
            }
        }
    }
}

// ============================================================================
// fp16 tensor-core causal flash attention (m16n8k16) — R8 version (plim skip
// reverted: data-dependent branches in the mma unroll broke pipelining).
// smem: Q/P [128][72] fp16 | K x2 [64][72] | V^T x2 [64][72] = 54 KB -> 2 CTA/SM
// ============================================================================
#define ASTRH 72
#define AQ_OFF    0
#define AK_OFF(b) (128 * ASTRH + (b) * 64 * ASTRH)
#define AV_OFF(b) (128 * ASTRH + 2 * 64 * ASTRH + (b) * 64 * ASTRH)
#define AT_H      (128 * ASTRH + 4 * 64 * ASTRH)
#define AT_BYTES  (AT_H * 2)                 // 55296

__global__ __launch_bounds__(256, 2) void attn_mma(
    const __half* __restrict__ Q, const __half* __restrict__ Kp,
    const __half* __restrict__ Vt, __half* __restrict__ O)
{
    extern __shared__ __half smh[];
    const int tid  = threadIdx.x;
    const int wid  = tid >> 5;
    const int lane = tid & 31;
    const int qt   = (SEQ / 128 - 1) - blockIdx.x;   // long blocks first
    const int h    = blockIdx.y;
    const int b    = blockIdx.z;
    const int q0   = qt * 128;
    const int nkt  = 2 * qt + 2;
    const size_t hb = (size_t)b * SEQ * D_MODEL + (size_t)h * DH;

    auto load_k = [&](int kt, int buf) {
        uint32_t dst = smem_u32(smh + AK_OFF(buf));
        const __half* Kg = Kp + hb + (size_t)kt * 64 * D_MODEL;
#pragma unroll
        for (int i = 0; i < 2; i++) {
            int chunk = tid + 256 * i;       // 0..511
            int row = chunk >> 3, c = chunk & 7;
            CP_ASYNC16(dst + (uint32_t)row * (ASTRH * 2) + c * 16,
                       __cvta_generic_to_global(Kg + (size_t)row * D_MODEL + c * 8));
        }
    };
    auto load_v = [&](int kt, int buf) {
        uint32_t dst = smem_u32(smh + AV_OFF(buf));
        const __half* Vg = Vt + (size_t)h * 64 * NTOK + (size_t)b * SEQ + (size_t)kt * 64;
#pragma unroll
        for (int i = 0; i < 2; i++) {
            int chunk = tid + 256 * i;
            int d = chunk >> 3, c = chunk & 7;
            CP_ASYNC16(dst + (uint32_t)d * (ASTRH * 2) + c * 16,
                       __cvta_generic_to_global(Vg + (size_t)d * NTOK + c * 8));
        }
    };

    // prologue: Q (group0), K0+V0 (group1)
    {
        uint32_t qdst = smem_u32(smh + AQ_OFF);
#pragma unroll
        for (int i = 0; i < 4; i++) {
            int chunk = tid + 256 * i;       // 0..1023
            int row = chunk >> 3, c = chunk & 7;
            CP_ASYNC16(qdst + (uint32_t)row * (ASTRH * 2) + c * 16,
                       __cvta_generic_to_global(Q + hb + (size_t)(q0 + row) * D_MODEL + c * 8));
        }
        CP_COMMIT();
    }
    load_k(0, 0);
    load_v(0, 0);
    CP_COMMIT();

    const int aj   = lane >> 3;
    const int mrow = ((aj & 1) << 3) + (lane & 7);
    const int mcol = (aj >> 1) << 4;
    const int wq   = wid * 16;

    CP_WAIT1();
    __syncthreads();

    // Preload Q fragments (pre-scaled in GEMM epilogue): 4 k16-steps
    uint32_t qfr[4][4];
    {
        uint32_t qa = smem_u32(smh + AQ_OFF) + (uint32_t)(wq + mrow) * (ASTRH * 2) + mcol;
#pragma unroll
        for (int ks = 0; ks < 4; ks++) ldsm_x4(qfr[ks], qa + ks * 32);
    }
    // Q smem region reused as P (all threads hold Q frags; pass loop-top sync)

    __half* Ps = smh + AQ_OFF;
    const uint32_t pLd = smem_u32(Ps) + (uint32_t)(wq + mrow) * (ASTRH * 2) + mcol;
    const uint32_t kB[2] = { smem_u32(smh + AK_OFF(0)) + (uint32_t)mrow * (ASTRH * 2) + mcol,
                             smem_u32(smh + AK_OFF(1)) + (uint32_t)mrow * (ASTRH * 2) + mcol };
    const uint32_t vB[2] = { smem_u32(smh + AV_OFF(0)) + (uint32_t)mrow * (ASTRH * 2) + mcol,
                             smem_u32(smh + AV_OFF(1)) + (uint32_t)mrow * (ASTRH * 2) + mcol };

    float oacc[8][4];
#pragma unroll
    for (int nt = 0; nt < 8; nt++)
#pragma unroll
        for (int r = 0; r < 4; r++) oacc[nt][r] = 0.f;
    float m0 = -INFINITY, m1 = -INFINITY, l0 = 0.f, l1 = 0.f;

    const int lr = lane >> 2;
    const int lc = (lane & 3) * 2;

    for (int kt = 0; kt < nkt; kt++) {
        const int buf = kt & 1;
        const int k0  = kt * 64;
        CP_WAIT0();
        __syncthreads();

        if (kt + 1 < nkt) {
            load_k(kt + 1, buf ^ 1);
            load_v(kt + 1, buf ^ 1);
            CP_COMMIT();
        }

        // ---- S = Q K^T : 4 ksteps x 4 p-tiles x 2 mmas = 32 mmas ----
        float sacc[8][4];
#pragma unroll
        for (int nt = 0; nt < 8; nt++)
#pragma unroll
            for (int r = 0; r < 4; r++) sacc[nt][r] = 0.f;

#pragma unroll
        for (int ks = 0; ks < 4; ks++) {
#pragma unroll
            for (int p = 0; p < 4; p++) {
                uint32_t kf[4];
                ldsm_x4(kf, kB[buf] + (uint32_t)(p * 16 * ASTRH * 2) + ks * 32);
                mma_f16(sacc[2 * p],     qfr[ks], kf[0], kf[2]);
                mma_f16(sacc[2 * p + 1], qfr[ks], kf[1], kf[3]);
            }
        }

        const int rg0 = q0 + wq + lr;
        if (kt >= 2 * qt) {
#pragma unroll
            for (int nt = 0; nt < 8; nt++) {
                int cb = k0 + nt * 8 + lc;
                if (cb     > rg0)     sacc[nt][0] = -1e30f;
                if (cb + 1 > rg0)     sacc[nt][1] = -1e30f;
                if (cb     > rg0 + 8) sacc[nt][2] = -1e30f;
                if (cb + 1 > rg0 + 8) sacc[nt][3] = -1e30f;
            }
        }

        // ---- online softmax (log2 domain) ----
        float mx0 = -1e30f, mx1 = -1e30f;
#pragma unroll
        for (int nt = 0; nt < 8; nt++) {
            mx0 = fmaxf(mx0, fmaxf(sacc[nt][0], sacc[nt][1]));
            mx1 = fmaxf(mx1, fmaxf(sacc[nt][2], sacc[nt][3]));
        }
        mx0 = fmaxf(mx0, __shfl_xor_sync(0xffffffffu, mx0, 1));
        mx0 = fmaxf(mx0, __shfl_xor_sync(0xffffffffu, mx0, 2));
        mx1 = fmaxf(mx1, __shfl_xor_sync(0xffffffffu, mx1, 1));
        mx1 = fmaxf(mx1, __shfl_xor_sync(0xffffffffu, mx1, 2));
        float mn0 = fmaxf(m0, mx0), mn1 = fmaxf(m1, mx1);
        float a0 = ex2(m0 - mn0), a1 = ex2(m1 - mn1);
        float rs0 = 0.f, rs1 = 0.f;
#pragma unroll
        for (int nt = 0; nt < 8; nt++) {
            float e0 = ex2(sacc[nt][0] - mn0);
            float e1 = ex2(sacc[nt][1] - mn0);
            float e2 = ex2(sacc[nt][2] - mn1);
            float e3 = ex2(sacc[nt][3] - mn1);
            sacc[nt][0] = e0; sacc[nt][1] = e1; sacc[nt][2] = e2; sacc[nt][3] = e3;
            rs0 += e0 + e1; rs1 += e2 + e3;
        }
        rs0 += __shfl_xor_sync(0xffffffffu, rs0, 1);
        rs0 += __shfl_xor_sync(0xffffffffu, rs0, 2);
        rs1 += __shfl_xor_sync(0xffffffffu, rs1, 1);
        rs1 += __shfl_xor_sync(0xffffffffu, rs1, 2);
        l0 = l0 * a0 + rs0; m0 = mn0;
        l1 = l1 * a1 + rs1; m1 = mn1;
#pragma unroll
        for (int nt = 0; nt < 8; nt++) {
            oacc[nt][0] *= a0; oacc[nt][1] *= a0;
            oacc[nt][2] *= a1; oacc[nt][3] *= a1;
        }

        // ---- stash P as fp16 (warp-local rows) ----
        {
            __half* pr0 = Ps + (wq + lr) * ASTRH + lc;
            __half* pr1 = pr0 + 8 * ASTRH;
#pragma unroll
            for (int nt = 0; nt < 8; nt++) {
                *reinterpret_cast<__half2*>(pr0 + nt * 8)
                    = __floats2half2_rn(sacc[nt][0], sacc[nt][1]);
                *reinterpret_cast<__half2*>(pr1 + nt * 8)
                    = __floats2half2_rn(sacc[nt][2], sacc[nt][3]);
            }
        }
        __syncwarp();

        // ---- O += P V : 4 ksteps x 4 d-tiles x 2 mmas = 32 mmas ----
#pragma unroll
        for (int ks = 0; ks < 4; ks++) {
            uint32_t pf[4];
            ldsm_x4(pf, pLd + ks * 32);
#pragma unroll
            for (int p = 0; p < 4; p++) {
                uint32_t vf[4];
                ldsm_x4(vf, vB[buf] + (uint32_t)(p * 16 * ASTRH * 2) + ks * 32);
                mma_f16(oacc[2 * p],     pf, vf[0], vf[2]);
                mma_f16(oacc[2 * p + 1], pf, vf[1], vf[3]);
            }
        }
    }

    // ---- epilogue: fp16 ctx ----
    const float i0 = 1.f / l0, i1 = 1.f / l1;
    const int row0 = q0 + wq + lr;
    __half* Ob = O + (size_t)(b * SEQ + row0) * D_MODEL + (size_t)h * DH + lc;
#pragma unroll
    for (int nt = 0; nt < 8; nt++) {
        *reinterpret_cast<__half2*>(Ob + nt * 8)
            = __floats2half2_rn(oacc[nt][0] * i0, oacc[nt][1] * i0);
        *reinterpret_cast<__half2*>(Ob + 8 * D_MODEL + nt * 8)
            = __floats2half2_rn(oacc[nt][2] * i1, oacc[nt][3] * i1);
    }
}

// ---------------------------------------------------------------------------
extern "C" void kernel_launch(void* const* d_in, const int* in_sizes, int n_in,
                              void* d_out, int out_size)
{
    const float* x  = (const float*)d_in[0];
    const float* Wq = (const float*)d_in[1];
    const float* Wk = (const float*)d_in[2];
    const float* Wv = (const float*)d_in[3];
    const float* Wo = (const float*)d_in[4];
    float* out = (float*)d_out;

    __half *xh, *wqh, *wkh, *wvh, *woh, *q16, *k16, *vt16, *ctx;
    cudaGetSymbolAddress((void**)&xh,   g_xh);
    cudaGetSymbolAddress((void**)&wqh,  g_wqh);
    cudaGetSymbolAddress((void**)&wkh,  g_wkh);
    cudaGetSymbolAddress((void**)&wvh,  g_wvh);
    cudaGetSymbolAddress((void**)&woh,  g_woh);
    cudaGetSymbolAddress((void**)&q16,  g_q16);
    cudaGetSymbolAddress((void**)&k16,  g_k16);
    cudaGetSymbolAddress((void**)&vt16, g_vt16);
    cudaGetSymbolAddress((void**)&ctx,  g_ctx);

    cudaFuncSetAttribute(hgemm<0>, cudaFuncAttributeMaxDynamicSharedMemorySize, GSMEM_BYTES);
    cudaFuncSetAttribute(hgemm<1>, cudaFuncAttributeMaxDynamicSharedMemorySize, GSMEM_BYTES);
    cudaFuncSetAttribute(hgemm<2>, cudaFuncAttributeMaxDynamicSharedMemorySize, GSMEM_BYTES);
    cudaFuncSetAttribute(attn_mma, cudaFuncAttributeMaxDynamicSharedMemorySize, AT_BYTES);

    // fp32 -> fp16 conversions: 2 launches total
    const int NX = NTOK * D_MODEL, NW = D_MODEL * D_MODEL;
    f2h<<<NX / 1024, 256>>>(x, xh, NX);
    f2h4<<<dim3(NW / 1024, 4), 256>>>(Wq, Wk, Wv, Wo, wqh, wkh, wvh, woh, NW);

    dim3 gg (D_MODEL / BN, NTOK / BM);   // (8, 32)  — token-major outputs
    dim3 ggT(NTOK / BN, D_MODEL / BM);   // (32, 8)  — V^T output

    hgemm<1><<<gg,  256, GSMEM_BYTES>>>(xh,  wqh, (void*)q16,  NTOK,    D_MODEL, D_MODEL);
    hgemm<2><<<gg,  256, GSMEM_BYTES>>>(xh,  wkh, (void*)k16,  NTOK,    D_MODEL, D_MODEL);
    hgemm<2><<<ggT, 256, GSMEM_BYTES>>>(wvh, xh,  (void*)vt16, D_MODEL, NTOK,    D_MODEL);

    attn_mma<<<dim3(SEQ / 128, NH, BATCH), 256, AT_BYTES>>>(q16, k16, vt16, ctx);

    hgemm<0><<<gg, 256, GSMEM_BYTES>>>(ctx, woh, (void*)out, NTOK, D_MODEL, D_MODEL);
}

// round 12
// speedup vs baseline: 1.0671x; 1.0480x over previous
#include <cuda_runtime.h>
#include <cuda_fp16.h>
#include <math.h>
#include <stdint.h>

#define D_MODEL 1024
#define NH      16
#define DH      64
#define BATCH   2
#define SEQ     2048
#define NTOK    (BATCH * SEQ)   // 4096

// Scratch (device globals — no runtime allocation allowed)
__device__ __half g_xh [NTOK * D_MODEL];       // x in fp16
__device__ __half g_wqh[D_MODEL * D_MODEL];
__device__ __half g_wkh[D_MODEL * D_MODEL];
__device__ __half g_wvh[D_MODEL * D_MODEL];
__device__ __half g_woh[D_MODEL * D_MODEL];
__device__ __half g_q16 [NTOK * D_MODEL];      // Q fp16, pre-scaled by 0.125*log2(e)
__device__ __half g_k16 [NTOK * D_MODEL];      // K fp16 [token][chan]
__device__ __half g_vt16[D_MODEL * NTOK];      // V^T fp16 [chan][token]
__device__ __half g_ctx [NTOK * D_MODEL];      // attention output fp16

__device__ __forceinline__ uint32_t smem_u32(const void* p) {
    uint32_t a;
    asm("{ .reg .u64 t; cvta.to.shared.u64 t, %1; cvt.u32.u64 %0, t; }" : "=r"(a) : "l"(p));
    return a;
}
__device__ __forceinline__ void ldsm_x4(uint32_t (&r)[4], uint32_t addr) {
    asm volatile("ldmatrix.sync.aligned.m8n8.x4.shared.b16 {%0,%1,%2,%3}, [%4];"
                 : "=r"(r[0]), "=r"(r[1]), "=r"(r[2]), "=r"(r[3]) : "r"(addr));
}
// fp16 mma with fp32 accumulate
__device__ __forceinline__ void mma_f16(float (&c)[4], const uint32_t a[4],
                                        uint32_t b0, uint32_t b1) {
    asm volatile(
        "mma.sync.aligned.m16n8k16.row.col.f32.f16.f16.f32 "
        "{%0,%1,%2,%3}, {%4,%5,%6,%7}, {%8,%9}, {%0,%1,%2,%3};"
        : "+f"(c[0]), "+f"(c[1]), "+f"(c[2]), "+f"(c[3])
        : "r"(a[0]), "r"(a[1]), "r"(a[2]), "r"(a[3]), "r"(b0), "r"(b1));
}
__device__ __forceinline__ float ex2(float x) {
    float y; asm("ex2.approx.f32 %0, %1;" : "=f"(y) : "f"(x)); return y;
}
#define CP_ASYNC16(dst, src) \
    asm volatile("cp.async.cg.shared.global [%0], [%1], 16;" :: "r"(dst), "l"(src) : "memory")
#define CP_COMMIT() asm volatile("cp.async.commit_group;" ::: "memory")
#define CP_WAIT0()  asm volatile("cp.async.wait_group 0;" ::: "memory")
#define CP_WAIT1()  asm volatile("cp.async.wait_group 1;" ::: "memory")

// ============================================================================
// fp32 -> fp16 conversion. Single-tensor variant (x) and 4-way variant (Ws).
// ============================================================================
__global__ __launch_bounds__(256) void f2h(const float* __restrict__ in,
                                           __half* __restrict__ out, int n)
{
    int i = (blockIdx.x * 256 + threadIdx.x) * 4;
    if (i < n) {
        float4 v = *reinterpret_cast<const float4*>(in + i);
        __half2 h0 = __floats2half2_rn(v.x, v.y);
        __half2 h1 = __floats2half2_rn(v.z, v.w);
        uint2 pk = make_uint2(*reinterpret_cast<uint32_t*>(&h0),
                              *reinterpret_cast<uint32_t*>(&h1));
        *reinterpret_cast<uint2*>(out + i) = pk;
    }
}
__global__ __launch_bounds__(256) void f2h4(
    const float* __restrict__ i0, const float* __restrict__ i1,
    const float* __restrict__ i2, const float* __restrict__ i3,
    __half* __restrict__ o0, __half* __restrict__ o1,
    __half* __restrict__ o2, __half* __restrict__ o3, int n)
{
    const float* in  = (blockIdx.y == 0) ? i0 : (blockIdx.y == 1) ? i1
                     : (blockIdx.y == 2) ? i2 : i3;
    __half* out      = (blockIdx.y == 0) ? o0 : (blockIdx.y == 1) ? o1
                     : (blockIdx.y == 2) ? o2 : o3;
    int i = (blockIdx.x * 256 + threadIdx.x) * 4;
    if (i < n) {
        float4 v = *reinterpret_cast<const float4*>(in + i);
        __half2 h0 = __floats2half2_rn(v.x, v.y);
        __half2 h1 = __floats2half2_rn(v.z, v.w);
        uint2 pk = make_uint2(*reinterpret_cast<uint32_t*>(&h0),
                              *reinterpret_cast<uint32_t*>(&h1));
        *reinterpret_cast<uint2*>(out + i) = pk;
    }
}

// ============================================================================
// Shared fp16 GEMM body: C = A[M,K] @ W[N,K]^T tile (bm, bn).
// 2-stage cp.async double buffer, 256 threads, warp tile 64x32, K=1024.
// FP32OUT: write fp32 to Cv; else fp16 scaled by `scale`.
// ============================================================================
#define BM 128
#define BN 128
#define BKH 64
#define KSTRH 72                         // fp16 elems per smem row (144 B)
#define TILE_H (BM * KSTRH)              // fp16 per operand tile = 9216
#define GSMEM_BYTES (4 * TILE_H * 2)     // 73728
#define GK 1024

#define QSCALEF (0.125f * 1.4426950408889634f)

template <bool FP32OUT>
__device__ __forceinline__ void hgemm_body(
    __half* smh, const __half* __restrict__ A, const __half* __restrict__ W,
    void* __restrict__ Cv, int N, int bm, int bn, float scale)
{
    __half* AsP[2] = { smh,              smh + TILE_H };
    __half* BsP[2] = { smh + 2 * TILE_H, smh + 3 * TILE_H };

    const int tid  = threadIdx.x;
    const int wid  = tid >> 5;
    const int lane = tid & 31;
    const int wm = (wid >> 2) * 64;
    const int wn = (wid & 3) * 32;

    float acc[4][4][4];
#pragma unroll
    for (int i = 0; i < 4; i++)
#pragma unroll
        for (int j = 0; j < 4; j++)
#pragma unroll
            for (int q = 0; q < 4; q++) acc[i][j][q] = 0.f;

    const int aj   = lane >> 3;
    const int mrow = ((aj & 1) << 3) + (lane & 7);
    const int mcol = (aj >> 1) << 4;      // byte offset 0 or 16

    uint32_t aBase[2], bBase[2];
#pragma unroll
    for (int buf = 0; buf < 2; buf++) {
        aBase[buf] = smem_u32(AsP[buf]) + (uint32_t)(wm + mrow) * (KSTRH * 2) + mcol;
        bBase[buf] = smem_u32(BsP[buf]) + (uint32_t)(wn + mrow) * (KSTRH * 2) + mcol;
    }

    const __half* Ap = A + (size_t)bm * GK;
    const __half* Wp = W + (size_t)bn * GK;
    const int KT = GK / BKH;   // 16

    auto load_tile = [&](int t, int buf) {
        const __half* Ag = Ap + t * BKH;
        const __half* Bg = Wp + t * BKH;
        uint32_t sa = smem_u32(AsP[buf]);
        uint32_t sb = smem_u32(BsP[buf]);
#pragma unroll
        for (int i = 0; i < 4; i++) {
            int chunk = tid + 256 * i;       // 0..1023
            int row = chunk >> 3;
            int c   = chunk & 7;             // 16B chunk within 128B row
            uint32_t so = (uint32_t)row * (KSTRH * 2) + c * 16;
            CP_ASYNC16(sa + so, __cvta_generic_to_global(Ag + (size_t)row * GK + c * 8));
            CP_ASYNC16(sb + so, __cvta_generic_to_global(Bg + (size_t)row * GK + c * 8));
        }
        CP_COMMIT();
    };

    load_tile(0, 0);

    for (int t = 0; t < KT; t++) {
        const int buf = t & 1;
        if (t + 1 < KT) { load_tile(t + 1, buf ^ 1); CP_WAIT1(); }
        else           { CP_WAIT0(); }
        __syncthreads();

#pragma unroll
        for (int ks = 0; ks < 4; ks++) {          // 4 x k16 per BK=64
            uint32_t afr[4][4], bfr[2][4];
#pragma unroll
            for (int mt = 0; mt < 4; mt++)
                ldsm_x4(afr[mt], aBase[buf] + (uint32_t)(mt * 16 * KSTRH * 2) + ks * 32);
#pragma unroll
            for (int p = 0; p < 2; p++)
                ldsm_x4(bfr[p], bBase[buf] + (uint32_t)(p * 16 * KSTRH * 2) + ks * 32);
#pragma unroll
            for (int mt = 0; mt < 4; mt++) {
#pragma unroll
                for (int p = 0; p < 2; p++) {
                    mma_f16(acc[mt][2 * p],     afr[mt], bfr[p][0], bfr[p][2]);
                    mma_f16(acc[mt][2 * p + 1], afr[mt], bfr[p][1], bfr[p][3]);
                }
            }
        }
        __syncthreads();
    }

    const int rr = lane >> 2;
    const int cc = (lane & 3) * 2;
#pragma unroll
    for (int mt = 0; mt < 4; mt++) {
#pragma unroll
        for (int nt = 0; nt < 4; nt++) {
            int row = bm + wm + mt * 16 + rr;
            int col = bn + wn + nt * 8 + cc;
            if (FP32OUT) {
                float* Cp = (float*)Cv;
                *reinterpret_cast<float2*>(Cp + (size_t)row * N + col)
                    = make_float2(acc[mt][nt][0], acc[mt][nt][1]);
                *reinterpret_cast<float2*>(Cp + (size_t)(row + 8) * N + col)
                    = make_float2(acc[mt][nt][2], acc[mt][nt][3]);
            } else {
                __half* Cp = (__half*)Cv;
                __half2 v0 = __floats2half2_rn(acc[mt][nt][0] * scale, acc[mt][nt][1] * scale);
                __half2 v1 = __floats2half2_rn(acc[mt][nt][2] * scale, acc[mt][nt][3] * scale);
                *reinterpret_cast<__half2*>(Cp + (size_t)row * N + col)       = v0;
                *reinterpret_cast<__half2*>(Cp + (size_t)(row + 8) * N + col) = v1;
            }
        }
    }
}

// Merged Q/K/V^T GEMM: 768 CTAs in ONE launch (wave-merged, no streams).
// id<256: Q (scaled); id<512: K; else: V^T (A=Wv, W=x).
__global__ __launch_bounds__(256, 2) void qkv_gemm(
    const __half* __restrict__ xh,
    const __half* __restrict__ wqh, const __half* __restrict__ wkh,
    const __half* __restrict__ wvh,
    __half* __restrict__ q16, __half* __restrict__ k16, __half* __restrict__ vt16)
{
    extern __shared__ __half smh[];
    const int id = blockIdx.x;
    const __half *A, *W;
    __half* C;
    int N, bm, bn;
    float scale;
    if (id < 512) {
        A = xh;
        W = (id < 256) ? wqh : wkh;
        C = (id < 256) ? q16 : k16;
        scale = (id < 256) ? QSCALEF : 1.0f;
        int t = id & 255;
        bn = (t & 7) * BN;             // D_MODEL/128 = 8 tiles
        bm = (t >> 3) * BM;            // NTOK/128 = 32 tiles
        N = D_MODEL;
    } else {
        A = wvh; W = xh; C = vt16; scale = 1.0f;
        int t = id - 512;
        bn = (t & 31) * BN;            // NTOK/128 = 32 tiles
        bm = (t >> 5) * BM;            // D_MODEL/128 = 8 tiles
        N = NTOK;
    }
    hgemm_body<false>(smh, A, W, (void*)C, N, bm, bn, scale);
}

// Final output GEMM (fp32 out)
__global__ __launch_bounds__(256, 2) void out_gemm(
    const __half* __restrict__ ctx, const __half* __restrict__ woh,
    float* __restrict__ out)
{
    extern __shared__ __half smh[];
    int bn = (blockIdx.x & 7) * BN;
    int bm = (blockIdx.x >> 3) * BM;
    hgemm_body<true>(smh, ctx, woh, (void*)out, D_MODEL, bm, bn, 1.0f);
}

// ============================================================================
// fp16 tensor-core causal flash attention (m16n8k16) — R8 loop.
// smem: Q/P [128][72] fp16 | K x2 [64][72] | V^T x2 [64][72] = 54 KB -> 2 CTA/SM
// ============================================================================
#define ASTRH 72
#define AQ_OFF    0
#define AK_OFF(b) (128 * ASTRH + (b) * 64 * ASTRH)
#define AV_OFF(b) (128 * ASTRH + 2 * 64 * ASTRH + (b) * 64 * ASTRH)
#define AT_H      (128 * ASTRH + 4 * 64 * ASTRH)
#define AT_BYTES  (AT_H * 2)                 // 55296

__global__ __launch_bounds__(256, 2) void attn_mma(
    const __half* __restrict__ Q, const __half* __restrict__ Kp,
    const __half* __restrict__ Vt, __half* __restrict__ O)
{
    extern __shared__ __half smh[];
    const int tid  = threadIdx.x;
    const int wid  = tid >> 5;
    const int lane = tid & 31;
    const int qt   = (SEQ / 128 - 1) - blockIdx.x;   // long blocks first
    const int h    = blockIdx.y;
    const int b    = blockIdx.z;
    const int q0   = qt * 128;
    const int nkt  = 2 * qt + 2;
    const size_t hb = (size_t)b * SEQ * D_MODEL + (size_t)h * DH;

    auto load_k = [&](int kt, int buf) {
        uint32_t dst = smem_u32(smh + AK_OFF(buf));
        const __half* Kg = Kp + hb + (size_t)kt * 64 * D_MODEL;
#pragma unroll
        for (int i = 0; i < 2; i++) {
            int chunk = tid + 256 * i;       // 0..511
            int row = chunk >> 3, c = chunk & 7;
            CP_ASYNC16(dst + (uint32_t)row * (ASTRH * 2) + c * 16,
                       __cvta_generic_to_global(Kg + (size_t)row * D_MODEL + c * 8));
        }
    };
    auto load_v = [&](int kt, int buf) {
        uint32_t dst = smem_u32(smh + AV_OFF(buf));
        const __half* Vg = Vt + (size_t)h * 64 * NTOK + (size_t)b * SEQ + (size_t)kt * 64;
#pragma unroll
        for (int i = 0; i < 2; i++) {
            int chunk = tid + 256 * i;
            int d = chunk >> 3, c = chunk & 7;
            CP_ASYNC16(dst + (uint32_t)d * (ASTRH * 2) + c * 16,
                       __cvta_generic_to_global(Vg + (size_t)d * NTOK + c * 8));
        }
    };

    // prologue: Q (group0), K0+V0 (group1)
    {
        uint32_t qdst = smem_u32(smh + AQ_OFF);
#pragma unroll
        for (int i = 0; i < 4; i++) {
            int chunk = tid + 256 * i;       // 0..1023
            int row = chunk >> 3, c = chunk & 7;
            CP_ASYNC16(qdst + (uint32_t)row * (ASTRH * 2) + c * 16,
                       __cvta_generic_to_global(Q + hb + (size_t)(q0 + row) * D_MODEL + c * 8));
        }
        CP_COMMIT();
    }
    load_k(0, 0);
    load_v(0, 0);
    CP_COMMIT();

    const int aj   = lane >> 3;
    const int mrow = ((aj & 1) << 3) + (lane & 7);
    const int mcol = (aj >> 1) << 4;
    const int wq   = wid * 16;

    CP_WAIT1();
    __syncthreads();

    // Preload Q fragments (pre-scaled in GEMM epilogue): 4 k16-steps
    uint32_t qfr[4][4];
    {
        uint32_t qa = smem_u32(smh + AQ_OFF) + (uint32_t)(wq + mrow) * (ASTRH * 2) + mcol;
#pragma unroll
        for (int ks = 0; ks < 4; ks++) ldsm_x4(qfr[ks], qa + ks * 32);
    }
    // Q smem region reused as P (all threads hold Q frags; pass loop-top sync)

    __half* Ps = smh + AQ_OFF;
    const uint32_t pLd = smem_u32(Ps) + (uint32_t)(wq + mrow) * (ASTRH * 2) + mcol;
    const uint32_t kB[2] = { smem_u32(smh + AK_OFF(0)) + (uint32_t)mrow * (ASTRH * 2) + mcol,
                             smem_u32(smh + AK_OFF(1)) + (uint32_t)mrow * (ASTRH * 2) + mcol };
    const uint32_t vB[2] = { smem_u32(smh + AV_OFF(0)) + (uint32_t)mrow * (ASTRH * 2) + mcol,
                             smem_u32(smh + AV_OFF(1)) + (uint32_t)mrow * (ASTRH * 2) + mcol };

    float oacc[8][4];
#pragma unroll
    for (int nt = 0; nt < 8; nt++)
#pragma unroll
        for (int r = 0; r < 4; r++) oacc[nt][r] = 0.f;
    float m0 = -INFINITY, m1 = -INFINITY, l0 = 0.f, l1 = 0.f;

    const int lr = lane >> 2;
    const int lc = (lane & 3) * 2;

    for (int kt = 0; kt < nkt; kt++) {
        const int buf = kt & 1;
        const int k0  = kt * 64;
        CP_WAIT0();
        __syncthreads();

        if (kt + 1 < nkt) {
            load_k(kt + 1, buf ^ 1);
            load_v(kt + 1, buf ^ 1);
            CP_COMMIT();
        }

        // ---- S = Q K^T : 4 ksteps x 4 p-tiles x 2 mmas = 32 mmas ----
        float sacc[8][4];
#pragma unroll
        for (int nt = 0; nt < 8; nt++)
#pragma unroll
            for (int r = 0; r < 4; r++) sacc[nt][r] = 0.f;

#pragma unroll
        for (int ks = 0; ks < 4; ks++) {
#pragma unroll
            for (int p = 0; p < 4; p++) {
                uint32_t kf[4];
                ldsm_x4(kf, kB[buf] + (uint32_t)(p * 16 * ASTRH * 2) + ks * 32);
                mma_f16(sacc[2 * p],     qfr[ks], kf[0], kf[2]);
                mma_f16(sacc[2 * p + 1], qfr[ks], kf[1], kf[3]);
            }
        }

        const int rg0 = q0 + wq + lr;
        if (kt >= 2 * qt) {
#pragma unroll
            for (int nt = 0; nt < 8; nt++) {
                int cb = k0 + nt * 8 + lc;
                if (cb     > rg0)     sacc[nt][0] = -1e30f;
                if (cb + 1 > rg0)     sacc[nt][1] = -1e30f;
                if (cb     > rg0 + 8) sacc[nt][2] = -1e30f;
                if (cb + 1 > rg0 + 8) sacc[nt][3] = -1e30f;
            }
        }

        // ---- online softmax (log2 domain) ----
        float mx0 = -1e30f, mx1 = -1e30f;
#pragma unroll
        for (int nt = 0; nt < 8; nt++) {
            mx0 = fmaxf(mx0, fmaxf(sacc[nt][0], sacc[nt][1]));
            mx1 = fmaxf(mx1, fmaxf(sacc[nt][2], sacc[nt][3]));
        }
        mx0 = fmaxf(mx0, __shfl_xor_sync(0xffffffffu, mx0, 1));
        mx0 = fmaxf(mx0, __shfl_xor_sync(0xffffffffu, mx0, 2));
        mx1 = fmaxf(mx1, __shfl_xor_sync(0xffffffffu, mx1, 1));
        mx1 = fmaxf(mx1, __shfl_xor_sync(0xffffffffu, mx1, 2));
        float mn0 = fmaxf(m0, mx0), mn1 = fmaxf(m1, mx1);
        float a0 = ex2(m0 - mn0), a1 = ex2(m1 - mn1);
        float rs0 = 0.f, rs1 = 0.f;
#pragma unroll
        for (int nt = 0; nt < 8; nt++) {
            float e0 = ex2(sacc[nt][0] - mn0);
            float e1 = ex2(sacc[nt][1] - mn0);
            float e2 = ex2(sacc[nt][2] - mn1);
            float e3 = ex2(sacc[nt][3] - mn1);
            sacc[nt][0] = e0; sacc[nt][1] = e1; sacc[nt][2] = e2; sacc[nt][3] = e3;
            rs0 += e0 + e1; rs1 += e2 + e3;
        }
        rs0 += __shfl_xor_sync(0xffffffffu, rs0, 1);
        rs0 += __shfl_xor_sync(0xffffffffu, rs0, 2);
        rs1 += __shfl_xor_sync(0xffffffffu, rs1, 1);
        rs1 += __shfl_xor_sync(0xffffffffu, rs1, 2);
        l0 = l0 * a0 + rs0; m0 = mn0;
        l1 = l1 * a1 + rs1; m1 = mn1;
#pragma unroll
        for (int nt = 0; nt < 8; nt++) {
            oacc[nt][0] *= a0; oacc[nt][1] *= a0;
            oacc[nt][2] *= a1; oacc[nt][3] *= a1;
        }

        // ---- stash P as fp16 (warp-local rows) ----
        {
            __half* pr0 = Ps + (wq + lr) * ASTRH + lc;
            __half* pr1 = pr0 + 8 * ASTRH;
#pragma unroll
            for (int nt = 0; nt < 8; nt++) {
                *reinterpret_cast<__half2*>(pr0 + nt * 8)
                    = __floats2half2_rn(sacc[nt][0], sacc[nt][1]);
                *reinterpret_cast<__half2*>(pr1 + nt * 8)
                    = __floats2half2_rn(sacc[nt][2], sacc[nt][3]);
            }
        }
        __syncwarp();

        // ---- O += P V : 4 ksteps x 4 d-tiles x 2 mmas = 32 mmas ----
#pragma unroll
        for (int ks = 0; ks < 4; ks++) {
            uint32_t pf[4];
            ldsm_x4(pf, pLd + ks * 32);
#pragma unroll
            for (int p = 0; p < 4; p++) {
                uint32_t vf[4];
                ldsm_x4(vf, vB[buf] + (uint32_t)(p * 16 * ASTRH * 2) + ks * 32);
                mma_f16(oacc[2 * p],     pf, vf[0], vf[2]);
                mma_f16(oacc[2 * p + 1], pf, vf[1], vf[3]);
            }
        }
    }

    // ---- epilogue: fp16 ctx ----
    const float i0 = 1.f / l0, i1 = 1.f / l1;
    const int row0 = q0 + wq + lr;
    __half* Ob = O + (size_t)(b * SEQ + row0) * D_MODEL + (size_t)h * DH + lc;
#pragma unroll
    for (int nt = 0; nt < 8; nt++) {
        *reinterpret_cast<__half2*>(Ob + nt * 8)
            = __floats2half2_rn(oacc[nt][0] * i0, oacc[nt][1] * i0);
        *reinterpret_cast<__half2*>(Ob + 8 * D_MODEL + nt * 8)
            = __floats2half2_rn(oacc[nt][2] * i1, oacc[nt][3] * i1);
    }
}

// ---------------------------------------------------------------------------
extern "C" void kernel_launch(void* const* d_in, const int* in_sizes, int n_in,
                              void* d_out, int out_size)
{
    const float* x  = (const float*)d_in[0];
    const float* Wq = (const float*)d_in[1];
    const float* Wk = (const float*)d_in[2];
    const float* Wv = (const float*)d_in[3];
    const float* Wo = (const float*)d_in[4];
    float* out = (float*)d_out;

    __half *xh, *wqh, *wkh, *wvh, *woh, *q16, *k16, *vt16, *ctx;
    cudaGetSymbolAddress((void**)&xh,   g_xh);
    cudaGetSymbolAddress((void**)&wqh,  g_wqh);
    cudaGetSymbolAddress((void**)&wkh,  g_wkh);
    cudaGetSymbolAddress((void**)&wvh,  g_wvh);
    cudaGetSymbolAddress((void**)&woh,  g_woh);
    cudaGetSymbolAddress((void**)&q16,  g_q16);
    cudaGetSymbolAddress((void**)&k16,  g_k16);
    cudaGetSymbolAddress((void**)&vt16, g_vt16);
    cudaGetSymbolAddress((void**)&ctx,  g_ctx);

    cudaFuncSetAttribute(qkv_gemm, cudaFuncAttributeMaxDynamicSharedMemorySize, GSMEM_BYTES);
    cudaFuncSetAttribute(out_gemm, cudaFuncAttributeMaxDynamicSharedMemorySize, GSMEM_BYTES);
    cudaFuncSetAttribute(attn_mma, cudaFuncAttributeMaxDynamicSharedMemorySize, AT_BYTES);

    // fp32 -> fp16 conversions: 2 launches
    const int NX = NTOK * D_MODEL, NW = D_MODEL * D_MODEL;
    f2h<<<NX / 1024, 256>>>(x, xh, NX);
    f2h4<<<dim3(NW / 1024, 4), 256>>>(Wq, Wk, Wv, Wo, wqh, wkh, wvh, woh, NW);

    // All three projection GEMMs in ONE wave-merged launch (768 CTAs)
    qkv_gemm<<<768, 256, GSMEM_BYTES>>>(xh, wqh, wkh, wvh, q16, k16, vt16);

    attn_mma<<<dim3(SEQ / 128, NH, BATCH), 256, AT_BYTES>>>(q16, k16, vt16, ctx);

    out_gemm<<<256, 256, GSMEM_BYTES>>>(ctx, woh, out);
}

// round 13
// speedup vs baseline: 1.1161x; 1.0459x over previous
#include <cuda_runtime.h>
#include <cuda_fp16.h>
#include <math.h>
#include <stdint.h>

#define D_MODEL 1024
#define NH      16
#define DH      64
#define BATCH   2
#define SEQ     2048
#define NTOK    (BATCH * SEQ)   // 4096

// Scratch (device globals — no runtime allocation allowed)
__device__ __half g_xh [NTOK * D_MODEL];       // x in fp16
__device__ __half g_wqh[D_MODEL * D_MODEL];
__device__ __half g_wkh[D_MODEL * D_MODEL];
__device__ __half g_wvh[D_MODEL * D_MODEL];
__device__ __half g_woh[D_MODEL * D_MODEL];
__device__ __half g_q16 [NTOK * D_MODEL];      // Q fp16, pre-scaled by 0.125*log2(e)
__device__ __half g_k16 [NTOK * D_MODEL];      // K fp16 [token][chan]
__device__ __half g_vt16[D_MODEL * NTOK];      // V^T fp16 [chan][token]
__device__ __half g_ctx [NTOK * D_MODEL];      // attention output fp16

__device__ __forceinline__ uint32_t smem_u32(const void* p) {
    uint32_t a;
    asm("{ .reg .u64 t; cvta.to.shared.u64 t, %1; cvt.u32.u64 %0, t; }" : "=r"(a) : "l"(p));
    return a;
}
__device__ __forceinline__ void ldsm_x4(uint32_t (&r)[4], uint32_t addr) {
    asm volatile("ldmatrix.sync.aligned.m8n8.x4.shared.b16 {%0,%1,%2,%3}, [%4];"
                 : "=r"(r[0]), "=r"(r[1]), "=r"(r[2]), "=r"(r[3]) : "r"(addr));
}
// fp16 mma with fp32 accumulate
__device__ __forceinline__ void mma_f16(float (&c)[4], const uint32_t a[4],
                                        uint32_t b0, uint32_t b1) {
    asm volatile(
        "mma.sync.aligned.m16n8k16.row.col.f32.f16.f16.f32 "
        "{%0,%1,%2,%3}, {%4,%5,%6,%7}, {%8,%9}, {%0,%1,%2,%3};"
        : "+f"(c[0]), "+f"(c[1]), "+f"(c[2]), "+f"(c[3])
        : "r"(a[0]), "r"(a[1]), "r"(a[2]), "r"(a[3]), "r"(b0), "r"(b1));
}
__device__ __forceinline__ float ex2(float x) {
    float y; asm("ex2.approx.f32 %0, %1;" : "=f"(y) : "f"(x)); return y;
}
__device__ __forceinline__ uint32_t pack_h2(float a, float b) {
    __half2 h = __floats2half2_rn(a, b);
    return *reinterpret_cast<uint32_t*>(&h);
}
#define CP_ASYNC16(dst, src) \
    asm volatile("cp.async.cg.shared.global [%0], [%1], 16;" :: "r"(dst), "l"(src) : "memory")
#define CP_COMMIT() asm volatile("cp.async.commit_group;" ::: "memory")
#define CP_WAIT0()  asm volatile("cp.async.wait_group 0;" ::: "memory")
#define CP_WAIT1()  asm volatile("cp.async.wait_group 1;" ::: "memory")

// ============================================================================
// fp32 -> fp16 conversion. Single-tensor variant (x) and 4-way variant (Ws).
// ============================================================================
__global__ __launch_bounds__(256) void f2h(const float* __restrict__ in,
                                           __half* __restrict__ out, int n)
{
    int i = (blockIdx.x * 256 + threadIdx.x) * 4;
    if (i < n) {
        float4 v = *reinterpret_cast<const float4*>(in + i);
        __half2 h0 = __floats2half2_rn(v.x, v.y);
        __half2 h1 = __floats2half2_rn(v.z, v.w);
        uint2 pk = make_uint2(*reinterpret_cast<uint32_t*>(&h0),
                              *reinterpret_cast<uint32_t*>(&h1));
        *reinterpret_cast<uint2*>(out + i) = pk;
    }
}
__global__ __launch_bounds__(256) void f2h4(
    const float* __restrict__ i0, const float* __restrict__ i1,
    const float* __restrict__ i2, const float* __restrict__ i3,
    __half* __restrict__ o0, __half* __restrict__ o1,
    __half* __restrict__ o2, __half* __restrict__ o3, int n)
{
    const float* in  = (blockIdx.y == 0) ? i0 : (blockIdx.y == 1) ? i1
                     : (blockIdx.y == 2) ? i2 : i3;
    __half* out      = (blockIdx.y == 0) ? o0 : (blockIdx.y == 1) ? o1
                     : (blockIdx.y == 2) ? o2 : o3;
    int i = (blockIdx.x * 256 + threadIdx.x) * 4;
    if (i < n) {
        float4 v = *reinterpret_cast<const float4*>(in + i);
        __half2 h0 = __floats2half2_rn(v.x, v.y);
        __half2 h1 = __floats2half2_rn(v.z, v.w);
        uint2 pk = make_uint2(*reinterpret_cast<uint32_t*>(&h0),
                              *reinterpret_cast<uint32_t*>(&h1));
        *reinterpret_cast<uint2*>(out + i) = pk;
    }
}

// ============================================================================
// Shared fp16 GEMM body: C = A[M,K] @ W[N,K]^T tile (bm, bn).
// 2-stage cp.async double buffer, 256 threads, warp tile 64x32, K=1024.
// ============================================================================
#define BM 128
#define BN 128
#define BKH 64
#define KSTRH 72                         // fp16 elems per smem row (144 B)
#define TILE_H (BM * KSTRH)              // fp16 per operand tile = 9216
#define GSMEM_BYTES (4 * TILE_H * 2)     // 73728
#define GK 1024

#define QSCALEF (0.125f * 1.4426950408889634f)

template <bool FP32OUT>
__device__ __forceinline__ void hgemm_body(
    __half* smh, const __half* __restrict__ A, const __half* __restrict__ W,
    void* __restrict__ Cv, int N, int bm, int bn, float scale)
{
    __half* AsP[2] = { smh,              smh + TILE_H };
    __half* BsP[2] = { smh + 2 * TILE_H, smh + 3 * TILE_H };

    const int tid  = threadIdx.x;
    const int wid  = tid >> 5;
    const int lane = tid & 31;
    const int wm = (wid >> 2) * 64;
    const int wn = (wid & 3) * 32;

    float acc[4][4][4];
#pragma unroll
    for (int i = 0; i < 4; i++)
#pragma unroll
        for (int j = 0; j < 4; j++)
#pragma unroll
            for (int q = 0; q < 4; q++) acc[i][j][q] = 0.f;

    const int aj   = lane >> 3;
    const int mrow = ((aj & 1) << 3) + (lane & 7);
    const int mcol = (aj >> 1) << 4;      // byte offset 0 or 16

    uint32_t aBase[2], bBase[2];
#pragma unroll
    for (int buf = 0; buf < 2; buf++) {
        aBase[buf] = smem_u32(AsP[buf]) + (uint32_t)(wm + mrow) * (KSTRH * 2) + mcol;
        bBase[buf] = smem_u32(BsP[buf]) + (uint32_t)(wn + mrow) * (KSTRH * 2) + mcol;
    }

    const __half* Ap = A + (size_t)bm * GK;
    const __half* Wp = W + (size_t)bn * GK;
    const int KT = GK / BKH;   // 16

    auto load_tile = [&](int t, int buf) {
        const __half* Ag = Ap + t * BKH;
        const __half* Bg = Wp + t * BKH;
        uint32_t sa = smem_u32(AsP[buf]);
        uint32_t sb = smem_u32(BsP[buf]);
#pragma unroll
        for (int i = 0; i < 4; i++) {
            int chunk = tid + 256 * i;       // 0..1023
            int row = chunk >> 3;
            int c   = chunk & 7;             // 16B chunk within 128B row
            uint32_t so = (uint32_t)row * (KSTRH * 2) + c * 16;
            CP_ASYNC16(sa + so, __cvta_generic_to_global(Ag + (size_t)row * GK + c * 8));
            CP_ASYNC16(sb + so, __cvta_generic_to_global(Bg + (size_t)row * GK + c * 8));
        }
        CP_COMMIT();
    };

    load_tile(0, 0);

    for (int t = 0; t < KT; t++) {
        const int buf = t & 1;
        if (t + 1 < KT) { load_tile(t + 1, buf ^ 1); CP_WAIT1(); }
        else           { CP_WAIT0(); }
        __syncthreads();

#pragma unroll
        for (int ks = 0; ks < 4; ks++) {          // 4 x k16 per BK=64
            uint32_t afr[4][4], bfr[2][4];
#pragma unroll
            for (int mt = 0; mt < 4; mt++)
                ldsm_x4(afr[mt], aBase[buf] + (uint32_t)(mt * 16 * KSTRH * 2) + ks * 32);
#pragma unroll
            for (int p = 0; p < 2; p++)
                ldsm_x4(bfr[p], bBase[buf] + (uint32_t)(p * 16 * KSTRH * 2) + ks * 32);
#pragma unroll
            for (int mt = 0; mt < 4; mt++) {
#pragma unroll
                for (int p = 0; p < 2; p++) {
                    mma_f16(acc[mt][2 * p],     afr[mt], bfr[p][0], bfr[p][2]);
                    mma_f16(acc[mt][2 * p + 1], afr[mt], bfr[p][1], bfr[p][3]);
                }
            }
        }
        __syncthreads();
    }

    const int rr = lane >> 2;
    const int cc = (lane & 3) * 2;
#pragma unroll
    for (int mt = 0; mt < 4; mt++) {
#pragma unroll
        for (int nt = 0; nt < 4; nt++) {
            int row = bm + wm + mt * 16 + rr;
            int col = bn + wn + nt * 8 + cc;
            if (FP32OUT) {
                float* Cp = (float*)Cv;
                *reinterpret_cast<float2*>(Cp + (size_t)row * N + col)
                    = make_float2(acc[mt][nt][0], acc[mt][nt][1]);
                *reinterpret_cast<float2*>(Cp + (size_t)(row + 8) * N + col)
                    = make_float2(acc[mt][nt][2], acc[mt][nt][3]);
            } else {
                __half* Cp = (__half*)Cv;
                __half2 v0 = __floats2half2_rn(acc[mt][nt][0] * scale, acc[mt][nt][1] * scale);
                __half2 v1 = __floats2half2_rn(acc[mt][nt][2] * scale, acc[mt][nt][3] * scale);
                *reinterpret_cast<__half2*>(Cp + (size_t)row * N + col)       = v0;
                *reinterpret_cast<__half2*>(Cp + (size_t)(row + 8) * N + col) = v1;
            }
        }
    }
}

// Merged Q/K/V^T GEMM: 768 CTAs in ONE launch (wave-merged, no streams).
__global__ __launch_bounds__(256, 2) void qkv_gemm(
    const __half* __restrict__ xh,
    const __half* __restrict__ wqh, const __half* __restrict__ wkh,
    const __half* __restrict__ wvh,
    __half* __restrict__ q16, __half* __restrict__ k16, __half* __restrict__ vt16)
{
    extern __shared__ __half smh[];
    const int id = blockIdx.x;
    const __half *A, *W;
    __half* C;
    int N, bm, bn;
    float scale;
    if (id < 512) {
        A = xh;
        W = (id < 256) ? wqh : wkh;
        C = (id < 256) ? q16 : k16;
        scale = (id < 256) ? QSCALEF : 1.0f;
        int t = id & 255;
        bn = (t & 7) * BN;
        bm = (t >> 3) * BM;
        N = D_MODEL;
    } else {
        A = wvh; W = xh; C = vt16; scale = 1.0f;
        int t = id - 512;
        bn = (t & 31) * BN;
        bm = (t >> 5) * BM;
        N = NTOK;
    }
    hgemm_body<false>(smh, A, W, (void*)C, N, bm, bn, scale);
}

// Final output GEMM (fp32 out)
__global__ __launch_bounds__(256, 2) void out_gemm(
    const __half* __restrict__ ctx, const __half* __restrict__ woh,
    float* __restrict__ out)
{
    extern __shared__ __half smh[];
    int bn = (blockIdx.x & 7) * BN;
    int bm = (blockIdx.x >> 3) * BM;
    hgemm_body<true>(smh, ctx, woh, (void*)out, D_MODEL, bm, bn, 1.0f);
}

// ============================================================================
// fp16 tensor-core causal flash attention (m16n8k16).
// R13: P kept in registers — the S accumulator fragment layout IS the A
// operand layout for P.V (pack c-pairs to half2). No P smem round-trip.
// smem: Q [128][72] fp16 | K x2 [64][72] | V^T x2 [64][72] = 54 KB -> 2 CTA/SM
// ============================================================================
#define ASTRH 72
#define AQ_OFF    0
#define AK_OFF(b) (128 * ASTRH + (b) * 64 * ASTRH)
#define AV_OFF(b) (128 * ASTRH + 2 * 64 * ASTRH + (b) * 64 * ASTRH)
#define AT_H      (128 * ASTRH + 4 * 64 * ASTRH)
#define AT_BYTES  (AT_H * 2)                 // 55296

__global__ __launch_bounds__(256, 2) void attn_mma(
    const __half* __restrict__ Q, const __half* __restrict__ Kp,
    const __half* __restrict__ Vt, __half* __restrict__ O)
{
    extern __shared__ __half smh[];
    const int tid  = threadIdx.x;
    const int wid  = tid >> 5;
    const int lane = tid & 31;
    const int qt   = (SEQ / 128 - 1) - blockIdx.x;   // long blocks first
    const int h    = blockIdx.y;
    const int b    = blockIdx.z;
    const int q0   = qt * 128;
    const int nkt  = 2 * qt + 2;
    const size_t hb = (size_t)b * SEQ * D_MODEL + (size_t)h * DH;

    auto load_k = [&](int kt, int buf) {
        uint32_t dst = smem_u32(smh + AK_OFF(buf));
        const __half* Kg = Kp + hb + (size_t)kt * 64 * D_MODEL;
#pragma unroll
        for (int i = 0; i < 2; i++) {
            int chunk = tid + 256 * i;       // 0..511
            int row = chunk >> 3, c = chunk & 7;
            CP_ASYNC16(dst + (uint32_t)row * (ASTRH * 2) + c * 16,
                       __cvta_generic_to_global(Kg + (size_t)row * D_MODEL + c * 8));
        }
    };
    auto load_v = [&](int kt, int buf) {
        uint32_t dst = smem_u32(smh + AV_OFF(buf));
        const __half* Vg = Vt + (size_t)h * 64 * NTOK + (size_t)b * SEQ + (size_t)kt * 64;
#pragma unroll
        for (int i = 0; i < 2; i++) {
            int chunk = tid + 256 * i;
            int d = chunk >> 3, c = chunk & 7;
            CP_ASYNC16(dst + (uint32_t)d * (ASTRH * 2) + c * 16,
                       __cvta_generic_to_global(Vg + (size_t)d * NTOK + c * 8));
        }
    };

    // prologue: Q (group0), K0+V0 (group1)
    {
        uint32_t qdst = smem_u32(smh + AQ_OFF);
#pragma unroll
        for (int i = 0; i < 4; i++) {
            int chunk = tid + 256 * i;       // 0..1023
            int row = chunk >> 3, c = chunk & 7;
            CP_ASYNC16(qdst + (uint32_t)row * (ASTRH * 2) + c * 16,
                       __cvta_generic_to_global(Q + hb + (size_t)(q0 + row) * D_MODEL + c * 8));
        }
        CP_COMMIT();
    }
    load_k(0, 0);
    load_v(0, 0);
    CP_COMMIT();

    const int aj   = lane >> 3;
    const int mrow = ((aj & 1) << 3) + (lane & 7);
    const int mcol = (aj >> 1) << 4;
    const int wq   = wid * 16;

    CP_WAIT1();
    __syncthreads();

    // Preload Q fragments (pre-scaled in GEMM epilogue): 4 k16-steps
    uint32_t qfr[4][4];
    {
        uint32_t qa = smem_u32(smh + AQ_OFF) + (uint32_t)(wq + mrow) * (ASTRH * 2) + mcol;
#pragma unroll
        for (int ks = 0; ks < 4; ks++) ldsm_x4(qfr[ks], qa + ks * 32);
    }

    const uint32_t kB[2] = { smem_u32(smh + AK_OFF(0)) + (uint32_t)mrow * (ASTRH * 2) + mcol,
                             smem_u32(smh + AK_OFF(1)) + (uint32_t)mrow * (ASTRH * 2) + mcol };
    const uint32_t vB[2] = { smem_u32(smh + AV_OFF(0)) + (uint32_t)mrow * (ASTRH * 2) + mcol,
                             smem_u32(smh + AV_OFF(1)) + (uint32_t)mrow * (ASTRH * 2) + mcol };

    float oacc[8][4];
#pragma unroll
    for (int nt = 0; nt < 8; nt++)
#pragma unroll
        for (int r = 0; r < 4; r++) oacc[nt][r] = 0.f;
    float m0 = -INFINITY, m1 = -INFINITY, l0 = 0.f, l1 = 0.f;

    const int lr = lane >> 2;
    const int lc = (lane & 3) * 2;

    for (int kt = 0; kt < nkt; kt++) {
        const int buf = kt & 1;
        const int k0  = kt * 64;
        CP_WAIT0();
        __syncthreads();

        if (kt + 1 < nkt) {
            load_k(kt + 1, buf ^ 1);
            load_v(kt + 1, buf ^ 1);
            CP_COMMIT();
        }

        // ---- S = Q K^T : 4 ksteps x 4 p-tiles x 2 mmas = 32 mmas ----
        float sacc[8][4];
#pragma unroll
        for (int nt = 0; nt < 8; nt++)
#pragma unroll
            for (int r = 0; r < 4; r++) sacc[nt][r] = 0.f;

#pragma unroll
        for (int ks = 0; ks < 4; ks++) {
#pragma unroll
            for (int p = 0; p < 4; p++) {
                uint32_t kf[4];
                ldsm_x4(kf, kB[buf] + (uint32_t)(p * 16 * ASTRH * 2) + ks * 32);
                mma_f16(sacc[2 * p],     qfr[ks], kf[0], kf[2]);
                mma_f16(sacc[2 * p + 1], qfr[ks], kf[1], kf[3]);
            }
        }

        const int rg0 = q0 + wq + lr;
        if (kt >= 2 * qt) {
#pragma unroll
            for (int nt = 0; nt < 8; nt++) {
                int cb = k0 + nt * 8 + lc;
                if (cb     > rg0)     sacc[nt][0] = -1e30f;
                if (cb + 1 > rg0)     sacc[nt][1] = -1e30f;
                if (cb     > rg0 + 8) sacc[nt][2] = -1e30f;
                if (cb + 1 > rg0 + 8) sacc[nt][3] = -1e30f;
            }
        }

        // ---- online softmax (log2 domain) ----
        float mx0 = -1e30f, mx1 = -1e30f;
#pragma unroll
        for (int nt = 0; nt < 8; nt++) {
            mx0 = fmaxf(mx0, fmaxf(sacc[nt][0], sacc[nt][1]));
            mx1 = fmaxf(mx1, fmaxf(sacc[nt][2], sacc[nt][3]));
        }
        mx0 = fmaxf(mx0, __shfl_xor_sync(0xffffffffu, mx0, 1));
        mx0 = fmaxf(mx0, __shfl_xor_sync(0xffffffffu, mx0, 2));
        mx1 = fmaxf(mx1, __shfl_xor_sync(0xffffffffu, mx1, 1));
        mx1 = fmaxf(mx1, __shfl_xor_sync(0xffffffffu, mx1, 2));
        float mn0 = fmaxf(m0, mx0), mn1 = fmaxf(m1, mx1);
        float a0 = ex2(m0 - mn0), a1 = ex2(m1 - mn1);
        float rs0 = 0.f, rs1 = 0.f;
#pragma unroll
        for (int nt = 0; nt < 8; nt++) {
            float e0 = ex2(sacc[nt][0] - mn0);
            float e1 = ex2(sacc[nt][1] - mn0);
            float e2 = ex2(sacc[nt][2] - mn1);
            float e3 = ex2(sacc[nt][3] - mn1);
            sacc[nt][0] = e0; sacc[nt][1] = e1; sacc[nt][2] = e2; sacc[nt][3] = e3;
            rs0 += e0 + e1; rs1 += e2 + e3;
        }
        rs0 += __shfl_xor_sync(0xffffffffu, rs0, 1);
        rs0 += __shfl_xor_sync(0xffffffffu, rs0, 2);
        rs1 += __shfl_xor_sync(0xffffffffu, rs1, 1);
        rs1 += __shfl_xor_sync(0xffffffffu, rs1, 2);
        l0 = l0 * a0 + rs0; m0 = mn0;
        l1 = l1 * a1 + rs1; m1 = mn1;
#pragma unroll
        for (int nt = 0; nt < 8; nt++) {
            oacc[nt][0] *= a0; oacc[nt][1] *= a0;
            oacc[nt][2] *= a1; oacc[nt][3] *= a1;
        }

        // ---- O += P V : P fragments built directly from sacc registers.
        // A-frag for kstep ks = {pack(c0,c1), pack(c2,c3)} of S tiles 2ks, 2ks+1.
#pragma unroll
        for (int ks = 0; ks < 4; ks++) {
            uint32_t pf[4];
            pf[0] = pack_h2(sacc[2 * ks][0],     sacc[2 * ks][1]);
            pf[1] = pack_h2(sacc[2 * ks][2],     sacc[2 * ks][3]);
            pf[2] = pack_h2(sacc[2 * ks + 1][0], sacc[2 * ks + 1][1]);
            pf[3] = pack_h2(sacc[2 * ks + 1][2], sacc[2 * ks + 1][3]);
#pragma unroll
            for (int p = 0; p < 4; p++) {
                uint32_t vf[4];
                ldsm_x4(vf, vB[buf] + (uint32_t)(p * 16 * ASTRH * 2) + ks * 32);
                mma_f16(oacc[2 * p],     pf, vf[0], vf[2]);
                mma_f16(oacc[2 * p + 1], pf, vf[1], vf[3]);
            }
        }
    }

    // ---- epilogue: fp16 ctx ----
    const float i0 = 1.f / l0, i1 = 1.f / l1;
    const int row0 = q0 + wq + lr;
    __half* Ob = O + (size_t)(b * SEQ + row0) * D_MODEL + (size_t)h * DH + lc;
#pragma unroll
    for (int nt = 0; nt < 8; nt++) {
        *reinterpret_cast<__half2*>(Ob + nt * 8)
            = __floats2half2_rn(oacc[nt][0] * i0, oacc[nt][1] * i0);
        *reinterpret_cast<__half2*>(Ob + 8 * D_MODEL + nt * 8)
            = __floats2half2_rn(oacc[nt][2] * i1, oacc[nt][3] * i1);
    }
}

// ---------------------------------------------------------------------------
extern "C" void kernel_launch(void* const* d_in, const int* in_sizes, int n_in,
                              void* d_out, int out_size)
{
    const float* x  = (const float*)d_in[0];
    const float* Wq = (const float*)d_in[1];
    const float* Wk = (const float*)d_in[2];
    const float* Wv = (const float*)d_in[3];
    const float* Wo = (const float*)d_in[4];
    float* out = (float*)d_out;

    __half *xh, *wqh, *wkh, *wvh, *woh, *q16, *k16, *vt16, *ctx;
    cudaGetSymbolAddress((void**)&xh,   g_xh);
    cudaGetSymbolAddress((void**)&wqh,  g_wqh);
    cudaGetSymbolAddress((void**)&wkh,  g_wkh);
    cudaGetSymbolAddress((void**)&wvh,  g_wvh);
    cudaGetSymbolAddress((void**)&woh,  g_woh);
    cudaGetSymbolAddress((void**)&q16,  g_q16);
    cudaGetSymbolAddress((void**)&k16,  g_k16);
    cudaGetSymbolAddress((void**)&vt16, g_vt16);
    cudaGetSymbolAddress((void**)&ctx,  g_ctx);

    cudaFuncSetAttribute(qkv_gemm, cudaFuncAttributeMaxDynamicSharedMemorySize, GSMEM_BYTES);
    cudaFuncSetAttribute(out_gemm, cudaFuncAttributeMaxDynamicSharedMemorySize, GSMEM_BYTES);
    cudaFuncSetAttribute(attn_mma, cudaFuncAttributeMaxDynamicSharedMemorySize, AT_BYTES);

    // fp32 -> fp16 conversions: 2 launches
    const int NX = NTOK * D_MODEL, NW = D_MODEL * D_MODEL;
    f2h<<<NX / 1024, 256>>>(x, xh, NX);
    f2h4<<<dim3(NW / 1024, 4), 256>>>(Wq, Wk, Wv, Wo, wqh, wkh, wvh, woh, NW);

    // All three projection GEMMs in ONE wave-merged launch (768 CTAs)
    qkv_gemm<<<768, 256, GSMEM_BYTES>>>(xh, wqh, wkh, wvh, q16, k16, vt16);

    attn_mma<<<dim3(SEQ / 128, NH, BATCH), 256, AT_BYTES>>>(q16, k16, vt16, ctx);

    out_gemm<<<256, 256, GSMEM_BYTES>>>(ctx, woh, out);
}